// round 10
// baseline (speedup 1.0000x reference)
#include <cuda_runtime.h>
#include <cuda_fp16.h>
#include <cstddef>

// InvertedResidualBlockME, fused 2-kernel plan:
//   K1: x = relu6(bn1(feats @ W1))         -> g_x fp16 [N,192] (76.8MB, L2-resident)
//   K2: y = depthwise_sparse_gather(g_x)   9 x half2 row gathers, 4 pts/pass,
//       software-pipelined across the barriers; then
//       out = bn3(relu6(bn2(y)) @ W3) + feats   (packed fma.rn.f32x2 project)
// L2 policy: nbr read-once via __ldcs, out write-once via __stcs; g_x uses
// default .wb stores (L2-allocating) so the randomly-gathered g_x stays
// L2-resident while the streaming data evicts first.

#define EPSF 1e-5f
#define MAXN 200000
#define HDIM 192
#define K1PTS 64   // points per block in K1 (two 32-point tiles)
#define K2PTS 64   // points per block in K2 (16 passes of 4)

__device__ __half g_x[(size_t)MAXN * HDIM];   // fp16 intermediate

// ---- packed f32x2 helpers ----
__device__ __forceinline__ unsigned long long pk2(float x, float y) {
    unsigned long long r;
    asm("mov.b64 %0, {%1, %2};" : "=l"(r) : "f"(x), "f"(y));
    return r;
}
__device__ __forceinline__ void unpk2(unsigned long long v, float& x, float& y) {
    asm("mov.b64 {%0, %1}, %2;" : "=f"(x), "=f"(y) : "l"(v));
}
__device__ __forceinline__ unsigned long long fma2(
    unsigned long long a, unsigned long long b, unsigned long long c) {
    unsigned long long d;
    asm("fma.rn.f32x2 %0, %1, %2, %3;" : "=l"(d) : "l"(a), "l"(b), "l"(c));
    return d;
}
__device__ __forceinline__ unsigned long long add2(
    unsigned long long a, unsigned long long b) {
    unsigned long long d;
    asm("add.rn.f32x2 %0, %1, %2;" : "=l"(d) : "l"(a), "l"(b));
    return d;
}
__device__ __forceinline__ float relu6f(float x) {
    return fminf(fmaxf(x, 0.f), 6.f);
}

// ---------------------------------------------------------------------------
// K1: expand GEMM + BN1 + relu6 -> fp16. 192 threads (one h-channel each),
// 64 points/block as two 32-point tiles (amortizes W1 column reg-fill).
// Each tile: feats transposed [c][m], XOR-(c&28) swizzle: LDS.128 at
// 4-aligned m yields (f_m0..f_m3) for channel c as two native f32 pairs.
// ---------------------------------------------------------------------------
__global__ __launch_bounds__(192) void k_expand(
    const float* __restrict__ feats, const float* __restrict__ W1,
    const float* __restrict__ g1, const float* __restrict__ b1,
    const float* __restrict__ m1, const float* __restrict__ v1,
    int N)
{
    __shared__ __align__(16) float sft[2][32 * 32];

    const int tid = threadIdx.x;
    const int nb  = blockIdx.x * K1PTS;

    const int h = tid;
    unsigned long long w1p[32];               // duplicated (w,w) pairs
#pragma unroll
    for (int c = 0; c < 32; c++) { float w = W1[c * HDIM + h]; w1p[c] = pk2(w, w); }

    const float s1 = g1[h] * rsqrtf(v1[h] + EPSF);
    const float t1 = b1[h] - m1[h] * s1;

#pragma unroll
    for (int half = 0; half < 2; half++) {
        const int n0 = nb + 32 * half;
        if (n0 >= N) break;                   // uniform across block

        for (int i = tid; i < 1024; i += 192) {
            int m = i >> 5, c = i & 31;
            float f = (n0 + m < N) ? feats[(size_t)(n0 + m) * 32 + c] : 0.f;
            sft[half][c * 32 + (m ^ (c & 28))] = f;
        }
        __syncthreads();

        for (int q = 0; q < 8; q++) {         // quads of points
            const int m0 = 4 * q;
            if (n0 + m0 >= N) break;          // uniform across block
            unsigned long long a01 = pk2(0.f, 0.f), a23 = pk2(0.f, 0.f);
#pragma unroll
            for (int c = 0; c < 32; c++) {
                const ulonglong2 v = *reinterpret_cast<const ulonglong2*>(
                    &sft[half][c * 32 + (m0 ^ (c & 28))]);   // LDS.128 broadcast
                a01 = fma2(v.x, w1p[c], a01);
                a23 = fma2(v.y, w1p[c], a23);
            }
            float r[4];
            unpk2(a01, r[0], r[1]); unpk2(a23, r[2], r[3]);
#pragma unroll
            for (int j = 0; j < 4; j++) {
                if (n0 + m0 + j < N) {
                    float y = relu6f(fmaf(r[j], s1, t1));
                    g_x[(size_t)(n0 + m0 + j) * HDIM + h] = __float2half(y);
                }
            }
        }
        // double-buffered sft[half]: next half writes the other buffer, and
        // its own __syncthreads() orders them; no extra barrier needed here.
    }
}

// ---------------------------------------------------------------------------
// K2: gather conv + BN2 + relu6 + project GEMM (f32x2) + BN3 + residual.
// 192 threads, FOUR points per pass, gathers SOFTWARE-PIPELINED one pass ahead:
//  gather role:  thread (gp = tid/96, cp = tid%96) gathers channel pair
//                (2cp,2cp+1) for points 2gp, 2gp+1 of the pass (18 LDGs).
//                BN2 scale pre-folded into w2p; epilogue is relu6(acc + t2).
//  staging:      st2[h*2 + pp] = packed (t_{2pp}, t_{2pp+1}) for channel h.
//  project role: thread (warp w, lane l): out-channel l partials over
//                h in [32w,32w+32); LDS.128 reads both point-pairs; two
//                independent fma.rn.f32x2 chains.
//  reduce role:  64 threads, add.rn.f32x2 over the 6 warps' packed partials.
// ---------------------------------------------------------------------------
__global__ __launch_bounds__(192, 2) void k_fuse(
    const int*   __restrict__ nbr,
    const float* __restrict__ W2, const float* __restrict__ W3,
    const float* __restrict__ g2, const float* __restrict__ b2,
    const float* __restrict__ m2, const float* __restrict__ v2,
    const float* __restrict__ g3, const float* __restrict__ b3,
    const float* __restrict__ m3, const float* __restrict__ v3,
    const float* __restrict__ feats, float* __restrict__ out,
    int N)
{
    __shared__ int snbr[K2PTS * 9];
    __shared__ __align__(16) unsigned long long st2[HDIM * 2]; // [h][pp]
    __shared__ __align__(16) unsigned long long sp2[HDIM * 2]; // [tid][pp]

    const int tid = threadIdx.x;
    const int n0  = blockIdx.x * K2PTS;

    for (int i = tid; i < K2PTS * 9; i += 192) {
        int p = i / 9, k = i - p * 9;
        snbr[i] = (n0 + p < N) ? __ldcs(&nbr[(size_t)(n0 + p) * 9 + k]) : -1;
    }

    // gather-role constants; BN2 scale folded into the depthwise weights
    const int gp = tid / 96;          // 0 -> points {0,1}, 1 -> points {2,3}
    const int cp = tid % 96;
    const float s2a = g2[2 * cp]     * rsqrtf(v2[2 * cp]     + EPSF);
    const float s2b = g2[2 * cp + 1] * rsqrtf(v2[2 * cp + 1] + EPSF);
    const float t2a = b2[2 * cp]     - m2[2 * cp]     * s2a;
    const float t2b = b2[2 * cp + 1] - m2[2 * cp + 1] * s2b;
    float2 w2p[9];
#pragma unroll
    for (int k = 0; k < 9; k++) {
        float2 wv = *reinterpret_cast<const float2*>(&W2[k * HDIM + 2 * cp]);
        w2p[k] = make_float2(wv.x * s2a, wv.y * s2b);
    }

    // project-role constants
    const int w = tid >> 5, l = tid & 31;
    unsigned long long w3p[32];               // duplicated W3 pairs
#pragma unroll
    for (int i = 0; i < 32; i++) {
        float v = W3[(size_t)(w * 32 + i) * 32 + l];
        w3p[i] = pk2(v, v);
    }

    // reduce-role constants (threads 0..63)
    float s3 = 0.f, t3 = 0.f;
    if (tid < 64) {
        int c = tid & 31;
        s3 = g3[c] * rsqrtf(v3[c] + EPSF);
        t3 = b3[c] - m3[c] * s3;
    }
    __syncthreads();   // also covers snbr before first prefetch below

    const __half2 h2z = __half2half2(__ushort_as_half(0));
    __half2 hA[9], hB[9];

    // --- prologue: issue gathers for pass 0 ---
    {
        const int* nbA = &snbr[(2 * gp)     * 9];
        const int* nbB = &snbr[(2 * gp + 1) * 9];
#pragma unroll
        for (int k = 0; k < 9; k++) {
            int jA = nbA[k], jB = nbB[k];
            hA[k] = (jA >= 0) ? *reinterpret_cast<const __half2*>(
                        &g_x[(size_t)jA * HDIM + 2 * cp]) : h2z;
            hB[k] = (jB >= 0) ? *reinterpret_cast<const __half2*>(
                        &g_x[(size_t)jB * HDIM + 2 * cp]) : h2z;
        }
    }

    const int npass = K2PTS / 4;
    for (int q = 0; q < npass; q++) {
        const int n = n0 + 4 * q;
        if (n >= N) break;                     // uniform across block

        // --- consume prefetched gathers: depthwise accumulate (+folded BN2) ---
        float aA0 = 0.f, aA1 = 0.f, aB0 = 0.f, aB1 = 0.f;
#pragma unroll
        for (int k = 0; k < 9; k++) {
            float2 vA = __half22float2(hA[k]);
            float2 vB = __half22float2(hB[k]);
            aA0 = fmaf(vA.x, w2p[k].x, aA0);
            aA1 = fmaf(vA.y, w2p[k].y, aA1);
            aB0 = fmaf(vB.x, w2p[k].x, aB0);
            aB1 = fmaf(vB.y, w2p[k].y, aB1);
        }
        st2[(2 * cp)     * 2 + gp] = pk2(relu6f(aA0 + t2a), relu6f(aB0 + t2a));
        st2[(2 * cp + 1) * 2 + gp] = pk2(relu6f(aA1 + t2b), relu6f(aB1 + t2b));

        // --- issue next pass's gathers BEFORE the barrier (fly over proj) ---
        if (q + 1 < npass && n0 + 4 * (q + 1) < N) {
            const int* nbA = &snbr[(4 * (q + 1) + 2 * gp)     * 9];
            const int* nbB = &snbr[(4 * (q + 1) + 2 * gp + 1) * 9];
#pragma unroll
            for (int k = 0; k < 9; k++) {
                int jA = nbA[k], jB = nbB[k];
                hA[k] = (jA >= 0) ? *reinterpret_cast<const __half2*>(
                            &g_x[(size_t)jA * HDIM + 2 * cp]) : h2z;
                hB[k] = (jB >= 0) ? *reinterpret_cast<const __half2*>(
                            &g_x[(size_t)jB * HDIM + 2 * cp]) : h2z;
            }
        }
        __syncthreads();

        // --- project partials: LDS.128 both pairs, two fma2 chains ---
        unsigned long long acc0 = pk2(0.f, 0.f), acc1 = pk2(0.f, 0.f);
#pragma unroll
        for (int i = 0; i < 32; i++) {
            const ulonglong2 tv = *reinterpret_cast<const ulonglong2*>(
                &st2[(w * 32 + i) * 2]);          // LDS.128 broadcast
            acc0 = fma2(tv.x, w3p[i], acc0);
            acc1 = fma2(tv.y, w3p[i], acc1);
        }
        sp2[tid * 2]     = acc0;
        sp2[tid * 2 + 1] = acc1;
        __syncthreads();

        // --- reduce 6 warps, packed adds; pp = tid>>5 (points 2pp,2pp+1) ---
        if (tid < 64) {
            const int pp = tid >> 5, c = tid & 31;
            unsigned long long s = sp2[(0 * 32 + c) * 2 + pp];
            s = add2(s, sp2[(1 * 32 + c) * 2 + pp]);
            s = add2(s, sp2[(2 * 32 + c) * 2 + pp]);
            s = add2(s, sp2[(3 * 32 + c) * 2 + pp]);
            s = add2(s, sp2[(4 * 32 + c) * 2 + pp]);
            s = add2(s, sp2[(5 * 32 + c) * 2 + pp]);
            float sx, sy; unpk2(s, sx, sy);
            const int np0 = n + 2 * pp, np1 = n + 2 * pp + 1;
            if (np0 < N)
                __stcs(&out[(size_t)np0 * 32 + c],
                       fmaf(sx, s3, t3) + feats[(size_t)np0 * 32 + c]);
            if (np1 < N)
                __stcs(&out[(size_t)np1 * 32 + c],
                       fmaf(sy, s3, t3) + feats[(size_t)np1 * 32 + c]);
        }
        // st2 of pass q+1 written only after sync2(q) ordered this pass's
        // project reads; sp2 of q+1 only after sync1(q+1), which the reduce
        // threads gate. Prefetch touches only registers. Safe.
    }
}

// ---------------------------------------------------------------------------
extern "C" void kernel_launch(void* const* d_in, const int* in_sizes, int n_in,
                              void* d_out, int out_size)
{
    const float* feats = (const float*)d_in[0];
    const int*   nbr   = (const int*)  d_in[1];
    const float* W1    = (const float*)d_in[2];
    const float* W2    = (const float*)d_in[3];
    const float* W3    = (const float*)d_in[4];
    const float* g1 = (const float*)d_in[5],  *b1 = (const float*)d_in[6];
    const float* m1 = (const float*)d_in[7],  *v1 = (const float*)d_in[8];
    const float* g2 = (const float*)d_in[9],  *b2 = (const float*)d_in[10];
    const float* m2 = (const float*)d_in[11], *v2 = (const float*)d_in[12];
    const float* g3 = (const float*)d_in[13], *b3 = (const float*)d_in[14];
    const float* m3 = (const float*)d_in[15], *v3 = (const float*)d_in[16];
    float* out = (float*)d_out;

    int N = in_sizes[0] / 32;
    if (N > MAXN) N = MAXN;

    k_expand<<<(N + K1PTS - 1) / K1PTS, 192>>>(feats, W1, g1, b1, m1, v1, N);
    k_fuse<<<(N + K2PTS - 1) / K2PTS, 192>>>(nbr, W2, W3,
                                             g2, b2, m2, v2,
                                             g3, b3, m3, v3,
                                             feats, out, N);
}

// round 12
// speedup vs baseline: 1.1118x; 1.1118x over previous
#include <cuda_runtime.h>
#include <cuda_fp16.h>
#include <cstddef>

// InvertedResidualBlockME, fused 2-kernel plan:
//   K1: x = relu6(bn1(feats @ W1))         -> g_x fp16 [N,192]
//   K2: y = depthwise_sparse_gather(g_x)   9 x half2 row gathers, 4 pts/pass,
//       software-pipelined across the barriers; then
//       out = bn3(relu6(bn2(y)) @ W3) + feats   (packed fma.rn.f32x2 project)
// R10 profile: k_fuse was occupancy-bound (occ 18%, issue 43%, regs 136).
// Fix: W3 staged in smem instead of 64 regs of duplicated pairs; 4 blocks/SM.

#define EPSF 1e-5f
#define MAXN 200000
#define HDIM 192
#define K1PTS 64   // points per block in K1 (two 32-point tiles)
#define K2PTS 64   // points per block in K2 (16 passes of 4)

__device__ __half g_x[(size_t)MAXN * HDIM];   // fp16 intermediate

// ---- packed f32x2 helpers ----
__device__ __forceinline__ unsigned long long pk2(float x, float y) {
    unsigned long long r;
    asm("mov.b64 %0, {%1, %2};" : "=l"(r) : "f"(x), "f"(y));
    return r;
}
__device__ __forceinline__ unsigned long long dup2(float x) {
    unsigned long long r;
    asm("mov.b64 %0, {%1, %1};" : "=l"(r) : "f"(x));
    return r;
}
__device__ __forceinline__ void unpk2(unsigned long long v, float& x, float& y) {
    asm("mov.b64 {%0, %1}, %2;" : "=f"(x), "=f"(y) : "l"(v));
}
__device__ __forceinline__ unsigned long long fma2(
    unsigned long long a, unsigned long long b, unsigned long long c) {
    unsigned long long d;
    asm("fma.rn.f32x2 %0, %1, %2, %3;" : "=l"(d) : "l"(a), "l"(b), "l"(c));
    return d;
}
__device__ __forceinline__ unsigned long long add2(
    unsigned long long a, unsigned long long b) {
    unsigned long long d;
    asm("add.rn.f32x2 %0, %1, %2;" : "=l"(d) : "l"(a), "l"(b));
    return d;
}
__device__ __forceinline__ float relu6f(float x) {
    return fminf(fmaxf(x, 0.f), 6.f);
}

// ---------------------------------------------------------------------------
// K1: expand GEMM + BN1 + relu6 -> fp16. 192 threads (one h-channel each),
// 64 points/block as two 32-point tiles (amortizes W1 column reg-fill).
// Each tile: feats transposed [c][m], XOR-(c&28) swizzle: LDS.128 at
// 4-aligned m yields (f_m0..f_m3) for channel c as two native f32 pairs.
// ---------------------------------------------------------------------------
__global__ __launch_bounds__(192, 3) void k_expand(
    const float* __restrict__ feats, const float* __restrict__ W1,
    const float* __restrict__ g1, const float* __restrict__ b1,
    const float* __restrict__ m1, const float* __restrict__ v1,
    int N)
{
    __shared__ __align__(16) float sft[2][32 * 32];

    const int tid = threadIdx.x;
    const int nb  = blockIdx.x * K1PTS;

    const int h = tid;
    unsigned long long w1p[32];               // duplicated (w,w) pairs
#pragma unroll
    for (int c = 0; c < 32; c++) { float w = W1[c * HDIM + h]; w1p[c] = pk2(w, w); }

    const float s1 = g1[h] * rsqrtf(v1[h] + EPSF);
    const float t1 = b1[h] - m1[h] * s1;

#pragma unroll
    for (int half = 0; half < 2; half++) {
        const int n0 = nb + 32 * half;
        if (n0 >= N) break;                   // uniform across block

        for (int i = tid; i < 1024; i += 192) {
            int m = i >> 5, c = i & 31;
            float f = (n0 + m < N) ? feats[(size_t)(n0 + m) * 32 + c] : 0.f;
            sft[half][c * 32 + (m ^ (c & 28))] = f;
        }
        __syncthreads();

        for (int q = 0; q < 8; q++) {         // quads of points
            const int m0 = 4 * q;
            if (n0 + m0 >= N) break;          // uniform across block
            unsigned long long a01 = pk2(0.f, 0.f), a23 = pk2(0.f, 0.f);
#pragma unroll
            for (int c = 0; c < 32; c++) {
                const ulonglong2 v = *reinterpret_cast<const ulonglong2*>(
                    &sft[half][c * 32 + (m0 ^ (c & 28))]);   // LDS.128 broadcast
                a01 = fma2(v.x, w1p[c], a01);
                a23 = fma2(v.y, w1p[c], a23);
            }
            float r[4];
            unpk2(a01, r[0], r[1]); unpk2(a23, r[2], r[3]);
#pragma unroll
            for (int j = 0; j < 4; j++) {
                if (n0 + m0 + j < N) {
                    float y = relu6f(fmaf(r[j], s1, t1));
                    g_x[(size_t)(n0 + m0 + j) * HDIM + h] = __float2half(y);
                }
            }
        }
        // double-buffered sft[half]: next half writes the other buffer, and
        // its own __syncthreads() orders them; no extra barrier needed here.
    }
}

// ---------------------------------------------------------------------------
// K2: gather conv + BN2 + relu6 + project GEMM (f32x2) + BN3 + residual.
// 192 threads, FOUR points per pass, gathers SOFTWARE-PIPELINED one pass ahead.
// W3 lives in SMEM (24KB), not registers: project iter = LDS.32 (lane-consec,
// conflict-free) + mov.b64 dup + 2x fma.rn.f32x2. regs ~80 -> 4 blocks/SM.
// ---------------------------------------------------------------------------
__global__ __launch_bounds__(192, 4) void k_fuse(
    const int*   __restrict__ nbr,
    const float* __restrict__ W2, const float* __restrict__ W3,
    const float* __restrict__ g2, const float* __restrict__ b2,
    const float* __restrict__ m2, const float* __restrict__ v2,
    const float* __restrict__ g3, const float* __restrict__ b3,
    const float* __restrict__ m3, const float* __restrict__ v3,
    const float* __restrict__ feats, float* __restrict__ out,
    int N)
{
    __shared__ int snbr[K2PTS * 9];
    __shared__ __align__(16) unsigned long long st2[HDIM * 2]; // [h][pp]
    __shared__ __align__(16) unsigned long long sp2[HDIM * 2]; // [tid][pp]
    __shared__ __align__(16) float w3sm[HDIM * 32];            // full W3 copy

    const int tid = threadIdx.x;
    const int n0  = blockIdx.x * K2PTS;

    for (int i = tid; i < K2PTS * 9; i += 192) {
        int p = i / 9, k = i - p * 9;
        snbr[i] = (n0 + p < N) ? __ldcs(&nbr[(size_t)(n0 + p) * 9 + k]) : -1;
    }
    // stage W3 (192x32 f32 = 24KB), coalesced float4 copies
    {
        const float4* src = reinterpret_cast<const float4*>(W3);
        float4*       dst = reinterpret_cast<float4*>(w3sm);
        for (int i = tid; i < HDIM * 32 / 4; i += 192) dst[i] = src[i];
    }

    // gather-role constants; BN2 scale folded into the depthwise weights
    const int gp = tid / 96;          // 0 -> points {0,1}, 1 -> points {2,3}
    const int cp = tid % 96;
    const float s2a = g2[2 * cp]     * rsqrtf(v2[2 * cp]     + EPSF);
    const float s2b = g2[2 * cp + 1] * rsqrtf(v2[2 * cp + 1] + EPSF);
    const float t2a = b2[2 * cp]     - m2[2 * cp]     * s2a;
    const float t2b = b2[2 * cp + 1] - m2[2 * cp + 1] * s2b;
    float2 w2p[9];
#pragma unroll
    for (int k = 0; k < 9; k++) {
        float2 wv = *reinterpret_cast<const float2*>(&W2[k * HDIM + 2 * cp]);
        w2p[k] = make_float2(wv.x * s2a, wv.y * s2b);
    }

    // project-role constants: thread (warp w, lane l) -> w3sm rows 32w..32w+31, col l
    const int w = tid >> 5, l = tid & 31;
    const int wbase = w * 32 * 32 + l;        // w3sm[(w*32+i)*32 + l]

    // reduce-role constants (threads 0..63)
    float s3 = 0.f, t3 = 0.f;
    if (tid < 64) {
        int c = tid & 31;
        s3 = g3[c] * rsqrtf(v3[c] + EPSF);
        t3 = b3[c] - m3[c] * s3;
    }
    __syncthreads();   // covers snbr + w3sm before first use

    const __half2 h2z = __half2half2(__ushort_as_half(0));
    __half2 hA[9], hB[9];

    // --- prologue: issue gathers for pass 0 ---
    {
        const int* nbA = &snbr[(2 * gp)     * 9];
        const int* nbB = &snbr[(2 * gp + 1) * 9];
#pragma unroll
        for (int k = 0; k < 9; k++) {
            int jA = nbA[k], jB = nbB[k];
            hA[k] = (jA >= 0) ? *reinterpret_cast<const __half2*>(
                        &g_x[(size_t)jA * HDIM + 2 * cp]) : h2z;
            hB[k] = (jB >= 0) ? *reinterpret_cast<const __half2*>(
                        &g_x[(size_t)jB * HDIM + 2 * cp]) : h2z;
        }
    }

    const int npass = K2PTS / 4;
    for (int q = 0; q < npass; q++) {
        const int n = n0 + 4 * q;
        if (n >= N) break;                     // uniform across block

        // --- consume prefetched gathers: depthwise accumulate (+folded BN2) ---
        float aA0 = 0.f, aA1 = 0.f, aB0 = 0.f, aB1 = 0.f;
#pragma unroll
        for (int k = 0; k < 9; k++) {
            float2 vA = __half22float2(hA[k]);
            float2 vB = __half22float2(hB[k]);
            aA0 = fmaf(vA.x, w2p[k].x, aA0);
            aA1 = fmaf(vA.y, w2p[k].y, aA1);
            aB0 = fmaf(vB.x, w2p[k].x, aB0);
            aB1 = fmaf(vB.y, w2p[k].y, aB1);
        }
        st2[(2 * cp)     * 2 + gp] = pk2(relu6f(aA0 + t2a), relu6f(aB0 + t2a));
        st2[(2 * cp + 1) * 2 + gp] = pk2(relu6f(aA1 + t2b), relu6f(aB1 + t2b));

        // --- issue next pass's gathers BEFORE the barrier (fly over proj) ---
        if (q + 1 < npass && n0 + 4 * (q + 1) < N) {
            const int* nbA = &snbr[(4 * (q + 1) + 2 * gp)     * 9];
            const int* nbB = &snbr[(4 * (q + 1) + 2 * gp + 1) * 9];
#pragma unroll
            for (int k = 0; k < 9; k++) {
                int jA = nbA[k], jB = nbB[k];
                hA[k] = (jA >= 0) ? *reinterpret_cast<const __half2*>(
                            &g_x[(size_t)jA * HDIM + 2 * cp]) : h2z;
                hB[k] = (jB >= 0) ? *reinterpret_cast<const __half2*>(
                            &g_x[(size_t)jB * HDIM + 2 * cp]) : h2z;
            }
        }
        __syncthreads();

        // --- project partials: LDS.128 st2 pairs + LDS.32 w3 + dup + 2 fma2 ---
        unsigned long long acc0 = pk2(0.f, 0.f), acc1 = pk2(0.f, 0.f);
#pragma unroll
        for (int i = 0; i < 32; i++) {
            const ulonglong2 tv = *reinterpret_cast<const ulonglong2*>(
                &st2[(w * 32 + i) * 2]);          // LDS.128 broadcast
            const unsigned long long wv = dup2(w3sm[wbase + i * 32]); // LDS.32
            acc0 = fma2(tv.x, wv, acc0);
            acc1 = fma2(tv.y, wv, acc1);
        }
        sp2[tid * 2]     = acc0;
        sp2[tid * 2 + 1] = acc1;
        __syncthreads();

        // --- reduce 6 warps, packed adds; pp = tid>>5 (points 2pp,2pp+1) ---
        if (tid < 64) {
            const int pp = tid >> 5, c = tid & 31;
            unsigned long long s = sp2[(0 * 32 + c) * 2 + pp];
            s = add2(s, sp2[(1 * 32 + c) * 2 + pp]);
            s = add2(s, sp2[(2 * 32 + c) * 2 + pp]);
            s = add2(s, sp2[(3 * 32 + c) * 2 + pp]);
            s = add2(s, sp2[(4 * 32 + c) * 2 + pp]);
            s = add2(s, sp2[(5 * 32 + c) * 2 + pp]);
            float sx, sy; unpk2(s, sx, sy);
            const int np0 = n + 2 * pp, np1 = n + 2 * pp + 1;
            if (np0 < N)
                __stcs(&out[(size_t)np0 * 32 + c],
                       fmaf(sx, s3, t3) + feats[(size_t)np0 * 32 + c]);
            if (np1 < N)
                __stcs(&out[(size_t)np1 * 32 + c],
                       fmaf(sy, s3, t3) + feats[(size_t)np1 * 32 + c]);
        }
        // st2 of pass q+1 written only after sync2(q) ordered this pass's
        // project reads; sp2 of q+1 only after sync1(q+1), which the reduce
        // threads gate. Prefetch touches only registers. Safe.
    }
}

// ---------------------------------------------------------------------------
extern "C" void kernel_launch(void* const* d_in, const int* in_sizes, int n_in,
                              void* d_out, int out_size)
{
    const float* feats = (const float*)d_in[0];
    const int*   nbr   = (const int*)  d_in[1];
    const float* W1    = (const float*)d_in[2];
    const float* W2    = (const float*)d_in[3];
    const float* W3    = (const float*)d_in[4];
    const float* g1 = (const float*)d_in[5],  *b1 = (const float*)d_in[6];
    const float* m1 = (const float*)d_in[7],  *v1 = (const float*)d_in[8];
    const float* g2 = (const float*)d_in[9],  *b2 = (const float*)d_in[10];
    const float* m2 = (const float*)d_in[11], *v2 = (const float*)d_in[12];
    const float* g3 = (const float*)d_in[13], *b3 = (const float*)d_in[14];
    const float* m3 = (const float*)d_in[15], *v3 = (const float*)d_in[16];
    float* out = (float*)d_out;

    int N = in_sizes[0] / 32;
    if (N > MAXN) N = MAXN;

    k_expand<<<(N + K1PTS - 1) / K1PTS, 192>>>(feats, W1, g1, b1, m1, v1, N);
    k_fuse<<<(N + K2PTS - 1) / K2PTS, 192>>>(nbr, W2, W3,
                                             g2, b2, m2, v2,
                                             g3, b3, m3, v3,
                                             feats, out, N);
}

// round 13
// speedup vs baseline: 1.1200x; 1.0074x over previous
#include <cuda_runtime.h>
#include <cuda_fp16.h>
#include <cstddef>

// InvertedResidualBlockME, fused 2-kernel plan:
//   K1: x = relu6(bn1(feats @ W1))         -> g_x fp16 [N,192]
//   K2: y = depthwise_sparse_gather(g_x)   9 x half2 row gathers, 4 pts/pass,
//       software-pipelined across the barriers; then
//       out = bn3(relu6(bn2(y)) @ W3) + feats   (packed fma.rn.f32x2 project)
// R12 profile: k_fuse L1tex-bound (L1 75.5%, issue 54.8%, occ 35.1%).
// Fix: W3 transposed in smem w3t[l][h] (stride-196 pad) -> project reads w3
// as 8x LDS.128 per loop instead of 32x LDS.32.

#define EPSF 1e-5f
#define MAXN 200000
#define HDIM 192
#define K1PTS 64   // points per block in K1 (two 32-point tiles)
#define K2PTS 64   // points per block in K2 (16 passes of 4)
#define W3PITCH 196  // floats per lane-row of transposed W3 (196%32=4 -> no conflicts; 784B 16B-aligned)

__device__ __half g_x[(size_t)MAXN * HDIM];   // fp16 intermediate

// ---- packed f32x2 helpers ----
__device__ __forceinline__ unsigned long long pk2(float x, float y) {
    unsigned long long r;
    asm("mov.b64 %0, {%1, %2};" : "=l"(r) : "f"(x), "f"(y));
    return r;
}
__device__ __forceinline__ unsigned long long dup2(float x) {
    unsigned long long r;
    asm("mov.b64 %0, {%1, %1};" : "=l"(r) : "f"(x));
    return r;
}
__device__ __forceinline__ void unpk2(unsigned long long v, float& x, float& y) {
    asm("mov.b64 {%0, %1}, %2;" : "=f"(x), "=f"(y) : "l"(v));
}
__device__ __forceinline__ unsigned long long fma2(
    unsigned long long a, unsigned long long b, unsigned long long c) {
    unsigned long long d;
    asm("fma.rn.f32x2 %0, %1, %2, %3;" : "=l"(d) : "l"(a), "l"(b), "l"(c));
    return d;
}
__device__ __forceinline__ unsigned long long add2(
    unsigned long long a, unsigned long long b) {
    unsigned long long d;
    asm("add.rn.f32x2 %0, %1, %2;" : "=l"(d) : "l"(a), "l"(b));
    return d;
}
__device__ __forceinline__ float relu6f(float x) {
    return fminf(fmaxf(x, 0.f), 6.f);
}

// ---------------------------------------------------------------------------
// K1: expand GEMM + BN1 + relu6 -> fp16. 192 threads (one h-channel each),
// 64 points/block as two 32-point tiles (amortizes W1 column reg-fill).
// Each tile: feats transposed [c][m], XOR-(c&28) swizzle: LDS.128 at
// 4-aligned m yields (f_m0..f_m3) for channel c as two native f32 pairs.
// ---------------------------------------------------------------------------
__global__ __launch_bounds__(192, 3) void k_expand(
    const float* __restrict__ feats, const float* __restrict__ W1,
    const float* __restrict__ g1, const float* __restrict__ b1,
    const float* __restrict__ m1, const float* __restrict__ v1,
    int N)
{
    __shared__ __align__(16) float sft[2][32 * 32];

    const int tid = threadIdx.x;
    const int nb  = blockIdx.x * K1PTS;

    const int h = tid;
    unsigned long long w1p[32];               // duplicated (w,w) pairs
#pragma unroll
    for (int c = 0; c < 32; c++) { float w = W1[c * HDIM + h]; w1p[c] = pk2(w, w); }

    const float s1 = g1[h] * rsqrtf(v1[h] + EPSF);
    const float t1 = b1[h] - m1[h] * s1;

#pragma unroll
    for (int half = 0; half < 2; half++) {
        const int n0 = nb + 32 * half;
        if (n0 >= N) break;                   // uniform across block

        for (int i = tid; i < 1024; i += 192) {
            int m = i >> 5, c = i & 31;
            float f = (n0 + m < N) ? feats[(size_t)(n0 + m) * 32 + c] : 0.f;
            sft[half][c * 32 + (m ^ (c & 28))] = f;
        }
        __syncthreads();

        for (int q = 0; q < 8; q++) {         // quads of points
            const int m0 = 4 * q;
            if (n0 + m0 >= N) break;          // uniform across block
            unsigned long long a01 = pk2(0.f, 0.f), a23 = pk2(0.f, 0.f);
#pragma unroll
            for (int c = 0; c < 32; c++) {
                const ulonglong2 v = *reinterpret_cast<const ulonglong2*>(
                    &sft[half][c * 32 + (m0 ^ (c & 28))]);   // LDS.128 broadcast
                a01 = fma2(v.x, w1p[c], a01);
                a23 = fma2(v.y, w1p[c], a23);
            }
            float r[4];
            unpk2(a01, r[0], r[1]); unpk2(a23, r[2], r[3]);
#pragma unroll
            for (int j = 0; j < 4; j++) {
                if (n0 + m0 + j < N) {
                    float y = relu6f(fmaf(r[j], s1, t1));
                    g_x[(size_t)(n0 + m0 + j) * HDIM + h] = __float2half(y);
                }
            }
        }
        // double-buffered sft[half]: next half writes the other buffer, and
        // its own __syncthreads() orders them; no extra barrier needed here.
    }
}

// ---------------------------------------------------------------------------
// K2: gather conv + BN2 + relu6 + project GEMM (f32x2) + BN3 + residual.
// 192 threads, FOUR points per pass, gathers SOFTWARE-PIPELINED one pass ahead.
// W3 transposed in SMEM: w3t[l*196 + h]; project iter-group = 1x LDS.128 (w3)
// + 4x LDS.128 (st2 broadcast) + 4 dup movs + 8 fma2.
// ---------------------------------------------------------------------------
__global__ __launch_bounds__(192, 4) void k_fuse(
    const int*   __restrict__ nbr,
    const float* __restrict__ W2, const float* __restrict__ W3,
    const float* __restrict__ g2, const float* __restrict__ b2,
    const float* __restrict__ m2, const float* __restrict__ v2,
    const float* __restrict__ g3, const float* __restrict__ b3,
    const float* __restrict__ m3, const float* __restrict__ v3,
    const float* __restrict__ feats, float* __restrict__ out,
    int N)
{
    __shared__ int snbr[K2PTS * 9];
    __shared__ __align__(16) unsigned long long st2[HDIM * 2]; // [h][pp]
    __shared__ __align__(16) unsigned long long sp2[HDIM * 2]; // [tid][pp]
    __shared__ __align__(16) float w3t[32 * W3PITCH];          // transposed W3 [l][h]

    const int tid = threadIdx.x;
    const int n0  = blockIdx.x * K2PTS;

    for (int i = tid; i < K2PTS * 9; i += 192) {
        int p = i / 9, k = i - p * 9;
        snbr[i] = (n0 + p < N) ? __ldcs(&nbr[(size_t)(n0 + p) * 9 + k]) : -1;
    }
    // stage W3 transposed: w3t[l][h] = W3[h][l]; coalesced GMEM reads
    for (int i = tid; i < HDIM * 32; i += 192) {
        int hh = i >> 5, ll = i & 31;
        w3t[ll * W3PITCH + hh] = W3[i];
    }

    // gather-role constants; BN2 scale folded into the depthwise weights
    const int gp = tid / 96;          // 0 -> points {0,1}, 1 -> points {2,3}
    const int cp = tid % 96;
    const float s2a = g2[2 * cp]     * rsqrtf(v2[2 * cp]     + EPSF);
    const float s2b = g2[2 * cp + 1] * rsqrtf(v2[2 * cp + 1] + EPSF);
    const float t2a = b2[2 * cp]     - m2[2 * cp]     * s2a;
    const float t2b = b2[2 * cp + 1] - m2[2 * cp + 1] * s2b;
    float2 w2p[9];
#pragma unroll
    for (int k = 0; k < 9; k++) {
        float2 wv = *reinterpret_cast<const float2*>(&W2[k * HDIM + 2 * cp]);
        w2p[k] = make_float2(wv.x * s2a, wv.y * s2b);
    }

    // project-role constants: thread (warp w, lane l) -> w3t row l, cols 32w..32w+31
    const int w = tid >> 5, l = tid & 31;
    const float* w3row = &w3t[l * W3PITCH + w * 32];

    // reduce-role constants (threads 0..63)
    float s3 = 0.f, t3 = 0.f;
    if (tid < 64) {
        int c = tid & 31;
        s3 = g3[c] * rsqrtf(v3[c] + EPSF);
        t3 = b3[c] - m3[c] * s3;
    }
    __syncthreads();   // covers snbr + w3t before first use

    const __half2 h2z = __half2half2(__ushort_as_half(0));
    __half2 hA[9], hB[9];

    // --- prologue: issue gathers for pass 0 ---
    {
        const int* nbA = &snbr[(2 * gp)     * 9];
        const int* nbB = &snbr[(2 * gp + 1) * 9];
#pragma unroll
        for (int k = 0; k < 9; k++) {
            int jA = nbA[k], jB = nbB[k];
            hA[k] = (jA >= 0) ? *reinterpret_cast<const __half2*>(
                        &g_x[(size_t)jA * HDIM + 2 * cp]) : h2z;
            hB[k] = (jB >= 0) ? *reinterpret_cast<const __half2*>(
                        &g_x[(size_t)jB * HDIM + 2 * cp]) : h2z;
        }
    }

    const int npass = K2PTS / 4;
    for (int q = 0; q < npass; q++) {
        const int n = n0 + 4 * q;
        if (n >= N) break;                     // uniform across block

        // --- consume prefetched gathers: depthwise accumulate (+folded BN2) ---
        float aA0 = 0.f, aA1 = 0.f, aB0 = 0.f, aB1 = 0.f;
#pragma unroll
        for (int k = 0; k < 9; k++) {
            float2 vA = __half22float2(hA[k]);
            float2 vB = __half22float2(hB[k]);
            aA0 = fmaf(vA.x, w2p[k].x, aA0);
            aA1 = fmaf(vA.y, w2p[k].y, aA1);
            aB0 = fmaf(vB.x, w2p[k].x, aB0);
            aB1 = fmaf(vB.y, w2p[k].y, aB1);
        }
        st2[(2 * cp)     * 2 + gp] = pk2(relu6f(aA0 + t2a), relu6f(aB0 + t2a));
        st2[(2 * cp + 1) * 2 + gp] = pk2(relu6f(aA1 + t2b), relu6f(aB1 + t2b));

        // --- issue next pass's gathers BEFORE the barrier (fly over proj) ---
        if (q + 1 < npass && n0 + 4 * (q + 1) < N) {
            const int* nbA = &snbr[(4 * (q + 1) + 2 * gp)     * 9];
            const int* nbB = &snbr[(4 * (q + 1) + 2 * gp + 1) * 9];
#pragma unroll
            for (int k = 0; k < 9; k++) {
                int jA = nbA[k], jB = nbB[k];
                hA[k] = (jA >= 0) ? *reinterpret_cast<const __half2*>(
                            &g_x[(size_t)jA * HDIM + 2 * cp]) : h2z;
                hB[k] = (jB >= 0) ? *reinterpret_cast<const __half2*>(
                            &g_x[(size_t)jB * HDIM + 2 * cp]) : h2z;
            }
        }
        __syncthreads();

        // --- project partials: per 4 channels: 1 LDS.128 w3 + 4 LDS.128 st2 ---
        unsigned long long acc0 = pk2(0.f, 0.f), acc1 = pk2(0.f, 0.f);
#pragma unroll
        for (int i4 = 0; i4 < 8; i4++) {
            const float4 wv = *reinterpret_cast<const float4*>(&w3row[i4 * 4]);
            const unsigned long long wx = dup2(wv.x);
            const unsigned long long wy = dup2(wv.y);
            const unsigned long long wz = dup2(wv.z);
            const unsigned long long ww = dup2(wv.w);
            const ulonglong2 t0 = *reinterpret_cast<const ulonglong2*>(
                &st2[(w * 32 + i4 * 4 + 0) * 2]);
            const ulonglong2 t1 = *reinterpret_cast<const ulonglong2*>(
                &st2[(w * 32 + i4 * 4 + 1) * 2]);
            const ulonglong2 t2v = *reinterpret_cast<const ulonglong2*>(
                &st2[(w * 32 + i4 * 4 + 2) * 2]);
            const ulonglong2 t3v = *reinterpret_cast<const ulonglong2*>(
                &st2[(w * 32 + i4 * 4 + 3) * 2]);
            acc0 = fma2(t0.x,  wx, acc0);  acc1 = fma2(t0.y,  wx, acc1);
            acc0 = fma2(t1.x,  wy, acc0);  acc1 = fma2(t1.y,  wy, acc1);
            acc0 = fma2(t2v.x, wz, acc0);  acc1 = fma2(t2v.y, wz, acc1);
            acc0 = fma2(t3v.x, ww, acc0);  acc1 = fma2(t3v.y, ww, acc1);
        }
        sp2[tid * 2]     = acc0;
        sp2[tid * 2 + 1] = acc1;
        __syncthreads();

        // --- reduce 6 warps, packed adds; pp = tid>>5 (points 2pp,2pp+1) ---
        if (tid < 64) {
            const int pp = tid >> 5, c = tid & 31;
            unsigned long long s = sp2[(0 * 32 + c) * 2 + pp];
            s = add2(s, sp2[(1 * 32 + c) * 2 + pp]);
            s = add2(s, sp2[(2 * 32 + c) * 2 + pp]);
            s = add2(s, sp2[(3 * 32 + c) * 2 + pp]);
            s = add2(s, sp2[(4 * 32 + c) * 2 + pp]);
            s = add2(s, sp2[(5 * 32 + c) * 2 + pp]);
            float sx, sy; unpk2(s, sx, sy);
            const int np0 = n + 2 * pp, np1 = n + 2 * pp + 1;
            if (np0 < N)
                __stcs(&out[(size_t)np0 * 32 + c],
                       fmaf(sx, s3, t3) + feats[(size_t)np0 * 32 + c]);
            if (np1 < N)
                __stcs(&out[(size_t)np1 * 32 + c],
                       fmaf(sy, s3, t3) + feats[(size_t)np1 * 32 + c]);
        }
        // st2 of pass q+1 written only after sync2(q) ordered this pass's
        // project reads; sp2 of q+1 only after sync1(q+1), which the reduce
        // threads gate. Prefetch touches only registers. Safe.
    }
}

// ---------------------------------------------------------------------------
extern "C" void kernel_launch(void* const* d_in, const int* in_sizes, int n_in,
                              void* d_out, int out_size)
{
    const float* feats = (const float*)d_in[0];
    const int*   nbr   = (const int*)  d_in[1];
    const float* W1    = (const float*)d_in[2];
    const float* W2    = (const float*)d_in[3];
    const float* W3    = (const float*)d_in[4];
    const float* g1 = (const float*)d_in[5],  *b1 = (const float*)d_in[6];
    const float* m1 = (const float*)d_in[7],  *v1 = (const float*)d_in[8];
    const float* g2 = (const float*)d_in[9],  *b2 = (const float*)d_in[10];
    const float* m2 = (const float*)d_in[11], *v2 = (const float*)d_in[12];
    const float* g3 = (const float*)d_in[13], *b3 = (const float*)d_in[14];
    const float* m3 = (const float*)d_in[15], *v3 = (const float*)d_in[16];
    float* out = (float*)d_out;

    int N = in_sizes[0] / 32;
    if (N > MAXN) N = MAXN;

    k_expand<<<(N + K1PTS - 1) / K1PTS, 192>>>(feats, W1, g1, b1, m1, v1, N);
    k_fuse<<<(N + K2PTS - 1) / K2PTS, 192>>>(nbr, W2, W3,
                                             g2, b2, m2, v2,
                                             g3, b3, m3, v3,
                                             feats, out, N);
}